// round 2
// baseline (speedup 1.0000x reference)
#include <cuda_runtime.h>

// Problem shape (fixed by the reference):
//   query [64, 512, 512]  (n, d, c)  - c contiguous
//   key   [64, 512, 1024] (n, d, t)  - t contiguous
//   value [64, 512, 1024] (n, d, t)
//   valid_ratios [64]
//   out   [64, 512, 512]  (n, d, c)  - c contiguous
#define NBATCH 64
#define DDIM   512
#define CDIM   512
#define TDIM   1024
#define WDIM   128
#define SCALE_F 0.04419417382415922f   // 512^-0.5

// Scratch: logits / softmax weights, [n][c][t] fp32 (134 MB, static device global)
__device__ float g_logits[(size_t)NBATCH * CDIM * TDIM];

// Packed f32x2 FMA (Blackwell dual-issue fp32 pipe; FFMA-3reg alone is half rate)
#define FMA2(d, a, b) \
    asm("fma.rn.f32x2 %0, %1, %2, %0;" : "+l"(d) : "l"(a), "l"(b))

__device__ __forceinline__ unsigned long long pack_dup(float x) {
    unsigned long long r;
    unsigned int u = __float_as_uint(x);
    asm("mov.b64 %0, {%1, %2};" : "=l"(r) : "r"(u), "r"(u));
    return r;
}

// ============================================================================
// GEMM1: logits[n][c][t] = sum_d Q[n][d][c] * K[n][d][t]
// TN layout: A[k][m] (Q, lda=CDIM), B[k][n] (K, ldb=TDIM). Block tile 64(c) x 128(t), BK=16.
// 256 threads, thread tile 4(m) x 8(n) accumulated as 4x4 f32x2 pairs.
// ============================================================================
__global__ __launch_bounds__(256) void gemm1_kernel(const float* __restrict__ Q,
                                                    const float* __restrict__ Kmat) {
    const int n  = blockIdx.z;
    const int t0 = blockIdx.x * 128;
    const int c0 = blockIdx.y * 64;

    const float* Ab = Q    + (size_t)n * (DDIM * CDIM) + c0;
    const float* Bb = Kmat + (size_t)n * (DDIM * TDIM) + t0;
    float*       Cb = g_logits + (size_t)n * (CDIM * TDIM) + (size_t)c0 * TDIM + t0;

    __shared__ float As[16][64];
    __shared__ float Bs[16][128];

    const int tid = threadIdx.x;
    const int tx  = tid & 15;   // n-direction (t), 8 cols each
    const int ty  = tid >> 4;   // m-direction (c), 4 rows each

    unsigned long long acc[4][4];
    #pragma unroll
    for (int i = 0; i < 4; i++)
        #pragma unroll
        for (int j = 0; j < 4; j++) acc[i][j] = 0ull;

    const int ar  = tid >> 4, ac4 = tid & 15;   // As: 16 rows x 16 float4
    const int br  = tid >> 5, bc4 = tid & 31;   // Bs: 16 rows x 32 float4 (2 per thread)

    for (int k0 = 0; k0 < DDIM; k0 += 16) {
        *(float4*)&As[ar][ac4 * 4] =
            *(const float4*)(Ab + (size_t)(k0 + ar) * CDIM + ac4 * 4);
        *(float4*)&Bs[br][bc4 * 4] =
            *(const float4*)(Bb + (size_t)(k0 + br) * TDIM + bc4 * 4);
        *(float4*)&Bs[br + 8][bc4 * 4] =
            *(const float4*)(Bb + (size_t)(k0 + br + 8) * TDIM + bc4 * 4);
        __syncthreads();

        #pragma unroll
        for (int kk = 0; kk < 16; kk++) {
            float4 a = *(const float4*)&As[kk][ty * 4];
            unsigned long long b0 = *(const unsigned long long*)&Bs[kk][tx * 8 + 0];
            unsigned long long b1 = *(const unsigned long long*)&Bs[kk][tx * 8 + 2];
            unsigned long long b2 = *(const unsigned long long*)&Bs[kk][tx * 8 + 4];
            unsigned long long b3 = *(const unsigned long long*)&Bs[kk][tx * 8 + 6];
            float am[4] = {a.x, a.y, a.z, a.w};
            #pragma unroll
            for (int m = 0; m < 4; m++) {
                unsigned long long A2 = pack_dup(am[m]);
                FMA2(acc[m][0], A2, b0);
                FMA2(acc[m][1], A2, b1);
                FMA2(acc[m][2], A2, b2);
                FMA2(acc[m][3], A2, b3);
            }
        }
        __syncthreads();
    }

    #pragma unroll
    for (int m = 0; m < 4; m++) {
        const int row = ty * 4 + m;
        #pragma unroll
        for (int p = 0; p < 4; p++)
            *(unsigned long long*)(Cb + (size_t)row * TDIM + tx * 8 + p * 2) = acc[m][p];
    }
}

// ============================================================================
// Masked softmax over t, in place on g_logits. One warp per (n, c) row.
// Mask: column index within w (t mod 128) must be < valid_width[n].
// ============================================================================
__global__ __launch_bounds__(256) void softmax_kernel(const float* __restrict__ ratios) {
    const int warp = threadIdx.x >> 5;
    const int lane = threadIdx.x & 31;
    const int row  = blockIdx.x * 8 + warp;   // 0 .. 64*512-1
    const int n    = row >> 9;                // row / CDIM

    const float r = ratios[n];
    const int vw  = min(WDIM, (int)floorf((float)WDIM * r + 0.5f));

    float* p = g_logits + (size_t)row * TDIM;

    float v[32];
    float mx = -INFINITY;
    #pragma unroll
    for (int i = 0; i < 32; i++) {
        const int t = lane + i * 32;
        float x = p[t] * SCALE_F;
        if ((t & (WDIM - 1)) >= vw) x = -INFINITY;
        v[i] = x;
        mx = fmaxf(mx, x);
    }
    #pragma unroll
    for (int off = 16; off > 0; off >>= 1)
        mx = fmaxf(mx, __shfl_xor_sync(0xffffffffu, mx, off));

    float s = 0.0f;
    #pragma unroll
    for (int i = 0; i < 32; i++) {
        const float e = expf(v[i] - mx);   // expf(-inf - mx) == 0 handles mask
        v[i] = e;
        s += e;
    }
    #pragma unroll
    for (int off = 16; off > 0; off >>= 1)
        s += __shfl_xor_sync(0xffffffffu, s, off);

    const float inv = 1.0f / s;
    #pragma unroll
    for (int i = 0; i < 32; i++)
        p[lane + i * 32] = v[i] * inv;
}

// ============================================================================
// GEMM2: out[n][dd][c] = sum_t V[n][dd][t] * W[n][c][t]
// NT layout: A = V [m=dd][k=t], B = W [n=c][k=t]. Block tile 64(dd) x 128(c), BK=16.
// Transpose-on-smem-store into k-major tiles, then same inner loop as GEMM1.
// ============================================================================
__global__ __launch_bounds__(256) void gemm2_kernel(const float* __restrict__ V,
                                                    float* __restrict__ Out) {
    const int n   = blockIdx.z;
    const int cc0 = blockIdx.x * 128;   // n-dim (c)
    const int dd0 = blockIdx.y * 64;    // m-dim (dd)

    const float* Ab = V + (size_t)n * (DDIM * TDIM) + (size_t)dd0 * TDIM;
    const float* Bb = g_logits + (size_t)n * (CDIM * TDIM) + (size_t)cc0 * TDIM;
    float*       Cb = Out + (size_t)n * (DDIM * CDIM) + (size_t)dd0 * CDIM + cc0;

    // Padded k-major tiles: As ld=68 (16B-aligned rows), Bs ld=130 (8B-aligned rows)
    __shared__ float As[16 * 68];
    __shared__ float Bs[16 * 130];

    const int tid = threadIdx.x;
    const int tx  = tid & 15;   // n-direction (c), 8 each
    const int ty  = tid >> 4;   // m-direction (dd), 4 each

    unsigned long long acc[4][4];
    #pragma unroll
    for (int i = 0; i < 4; i++)
        #pragma unroll
        for (int j = 0; j < 4; j++) acc[i][j] = 0ull;

    const int am = tid >> 2, ak4 = tid & 3;   // A: 64 rows x 4 float4/row

    for (int k0 = 0; k0 < TDIM; k0 += 16) {
        {
            float4 vv = *(const float4*)(Ab + (size_t)am * TDIM + k0 + ak4 * 4);
            float f[4] = {vv.x, vv.y, vv.z, vv.w};
            #pragma unroll
            for (int j = 0; j < 4; j++)
                As[(ak4 * 4 + j) * 68 + am] = f[j];
        }
        #pragma unroll
        for (int jj = 0; jj < 2; jj++) {
            const int lin = tid + jj * 256;          // 0..511
            const int nn  = lin >> 2, k4 = lin & 3;  // 128 rows x 4 float4/row
            float4 vv = *(const float4*)(Bb + (size_t)nn * TDIM + k0 + k4 * 4);
            float f[4] = {vv.x, vv.y, vv.z, vv.w};
            #pragma unroll
            for (int j = 0; j < 4; j++)
                Bs[(k4 * 4 + j) * 130 + nn] = f[j];
        }
        __syncthreads();

        #pragma unroll
        for (int kk = 0; kk < 16; kk++) {
            float4 a = *(const float4*)&As[kk * 68 + ty * 4];
            unsigned long long b0 = *(const unsigned long long*)&Bs[kk * 130 + tx * 8 + 0];
            unsigned long long b1 = *(const unsigned long long*)&Bs[kk * 130 + tx * 8 + 2];
            unsigned long long b2 = *(const unsigned long long*)&Bs[kk * 130 + tx * 8 + 4];
            unsigned long long b3 = *(const unsigned long long*)&Bs[kk * 130 + tx * 8 + 6];
            float amv[4] = {a.x, a.y, a.z, a.w};
            #pragma unroll
            for (int m = 0; m < 4; m++) {
                unsigned long long A2 = pack_dup(amv[m]);
                FMA2(acc[m][0], A2, b0);
                FMA2(acc[m][1], A2, b1);
                FMA2(acc[m][2], A2, b2);
                FMA2(acc[m][3], A2, b3);
            }
        }
        __syncthreads();
    }

    #pragma unroll
    for (int m = 0; m < 4; m++) {
        const int row = ty * 4 + m;
        #pragma unroll
        for (int p = 0; p < 4; p++)
            *(unsigned long long*)(Cb + (size_t)row * CDIM + tx * 8 + p * 2) = acc[m][p];
    }
}

// ============================================================================
// Launch
// ============================================================================
extern "C" void kernel_launch(void* const* d_in, const int* in_sizes, int n_in,
                              void* d_out, int out_size) {
    const float* q      = (const float*)d_in[0];  // [64, 512, 512]
    const float* k      = (const float*)d_in[1];  // [64, 512, 1024]
    const float* v      = (const float*)d_in[2];  // [64, 512, 1024]
    const float* ratios = (const float*)d_in[3];  // [64]
    float* out = (float*)d_out;                   // [64, 512, 512]
    (void)in_sizes; (void)n_in; (void)out_size;

    dim3 g1(TDIM / 128, CDIM / 64, NBATCH);
    gemm1_kernel<<<g1, 256>>>(q, k);

    softmax_kernel<<<(NBATCH * CDIM) / 8, 256>>>(ratios);

    dim3 g2(CDIM / 128, DDIM / 64, NBATCH);
    gemm2_kernel<<<g2, 256>>>(v, out);
}

// round 6
// speedup vs baseline: 4.8397x; 4.8397x over previous
#include <cuda_runtime.h>
#include <cuda_bf16.h>
#include <cstdint>

// Shapes: query [64,512,512] (n,d,c); key/value [64,512,1024] (n,d,t); out [64,512,512]
#define NB 64
#define DD 512
#define CC 512
#define TT 1024
#define WDIM 128
#define SCALE_F 0.04419417382415922f   // 512^-0.5

// tcgen05 is an arch-SPECIFIC feature: only available when this compilation pass
// targets sm_103a/sm_100a (not plain compute_103). Fallback path otherwise.
#if defined(__CUDA_ARCH_FEAT_SM103_ALL) || defined(__CUDA_ARCH_FEAT_SM101_ALL) || \
    defined(__CUDA_ARCH_FEAT_SM100_ALL) || \
    (defined(__CUDA_ARCH_SPECIFIC__) && (__CUDA_ARCH_SPECIFIC__ >= 1000))
#define USE_TCGEN05 1
#else
#define USE_TCGEN05 0
#endif

// ---------------- scratch (device globals; no allocation) ----------------
__device__ float g_logits[(size_t)NB * CC * TT];                       // 134 MB
__device__ __align__(16) __nv_bfloat16 g_Qth[(size_t)NB * CC * DD];    // Qt[c][d] hi
__device__ __align__(16) __nv_bfloat16 g_Qtl[(size_t)NB * CC * DD];
__device__ __align__(16) __nv_bfloat16 g_Kth[(size_t)NB * TT * DD];    // Kt[t][d]
__device__ __align__(16) __nv_bfloat16 g_Ktl[(size_t)NB * TT * DD];
__device__ __align__(16) __nv_bfloat16 g_Vh [(size_t)NB * DD * TT];    // V[d][t]
__device__ __align__(16) __nv_bfloat16 g_Vl [(size_t)NB * DD * TT];
__device__ __align__(16) __nv_bfloat16 g_Wh [(size_t)NB * CC * TT];    // W[c][t]
__device__ __align__(16) __nv_bfloat16 g_Wl [(size_t)NB * CC * TT];

// ---------------- common helpers ----------------
__device__ __forceinline__ uint32_t smem_to_u32(const void* p) {
    uint32_t a;
    asm("{ .reg .u64 t; cvta.to.shared.u64 t, %1; cvt.u32.u64 %0, t; }" : "=r"(a) : "l"(p));
    return a;
}
__device__ __forceinline__ void split2(float x, __nv_bfloat16& h, __nv_bfloat16& l) {
    h = __float2bfloat16(x);
    l = __float2bfloat16(x - __bfloat162float(h));   // exact residual
}
#define FMA2(d, a, b) \
    asm("fma.rn.f32x2 %0, %1, %2, %0;" : "+l"(d) : "l"(a), "l"(b))
__device__ __forceinline__ unsigned long long pack_dup(float x) {
    unsigned long long r;
    unsigned int u = __float_as_uint(x);
    asm("mov.b64 %0, {%1, %2};" : "=l"(r) : "r"(u), "r"(u));
    return r;
}
__device__ __forceinline__ float2 bf2_to_f2(uint32_t u) {
    __nv_bfloat162 b = *reinterpret_cast<__nv_bfloat162*>(&u);
    return __bfloat1622float2(b);
}

#if USE_TCGEN05
// ---------------- PTX helpers (sm_103a-only pass) ----------------
__device__ __forceinline__ uint32_t elect_one_pred() {
    uint32_t pred;
    asm volatile("{\n\t.reg .pred p;\n\telect.sync _|p, 0xFFFFFFFF;\n\tselp.b32 %0, 1, 0, p;\n\t}" : "=r"(pred));
    return pred;
}
#define MBARRIER_INIT(a, c) \
    asm volatile("mbarrier.init.shared.b64 [%0], %1;" :: "r"((uint32_t)(a)), "r"((uint32_t)(c)) : "memory")
#define MBARRIER_INVAL(a) \
    asm volatile("mbarrier.inval.shared.b64 [%0];" :: "r"((uint32_t)(a)) : "memory")
#define MBARRIER_WAIT_PARITY(mbar_smem_addr, phase_parity) do { \
    uint32_t _mbar = (uint32_t)(mbar_smem_addr); \
    uint32_t _parity = (uint32_t)(phase_parity); \
    uint32_t _done; \
    asm volatile("{\n\t.reg .pred p;\n\t" \
        "mbarrier.try_wait.parity.acquire.cta.shared::cta.b64 p, [%1], %2;\n\t" \
        "selp.b32 %0, 1, 0, p;\n\t}" \
        : "=r"(_done) : "r"(_mbar), "r"(_parity) : "memory"); \
    if (!_done) { \
        asm volatile("{\n\t.reg .pred P1;\n\t" \
            "WAIT_LOOP_%=:\n\t" \
            "mbarrier.try_wait.parity.acquire.cta.shared::cta.b64 P1, [%0], %1, 0x989680;\n\t" \
            "@P1 bra.uni WAIT_DONE_%=;\n\t" \
            "bra.uni WAIT_LOOP_%=;\n\t" \
            "WAIT_DONE_%=:\n\t}" \
            :: "r"(_mbar), "r"(_parity) : "memory"); \
    } \
} while(0)
#define TCGEN05_ALLOC(sa, n) \
    asm volatile("tcgen05.alloc.cta_group::1.sync.aligned.shared::cta.b32 [%0], %1;" \
                 :: "r"((uint32_t)(sa)), "r"((uint32_t)(n)) : "memory")
#define TCGEN05_DEALLOC(t, n) \
    asm volatile("tcgen05.dealloc.cta_group::1.sync.aligned.b32 %0, %1;" :: "r"(t), "r"((uint32_t)(n)))
#define TCGEN05_RELINQUISH() \
    asm volatile("tcgen05.relinquish_alloc_permit.cta_group::1.sync.aligned;")
#define TCGEN05_COMMIT(a) \
    asm volatile("tcgen05.commit.cta_group::1.mbarrier::arrive::one.shared::cluster.b64 [%0];" \
                 :: "r"((uint32_t)(a)) : "memory")
#define TCGEN05_FENCE_AFTER()  asm volatile("tcgen05.fence::after_thread_sync;" ::: "memory")
#define TCGEN05_FENCE_BEFORE() asm volatile("tcgen05.fence::before_thread_sync;" ::: "memory")
#define TCGEN05_WAIT_LD()      asm volatile("tcgen05.wait::ld.sync.aligned;" ::: "memory")
#define FENCE_PROXY_ASYNC()    asm volatile("fence.proxy.async.shared::cta;" ::: "memory")

#define TCGEN05_LD_32X32B_X32(r, ta) \
    asm volatile( \
        "tcgen05.ld.sync.aligned.32x32b.x32.b32 " \
        "{%0, %1, %2, %3, %4, %5, %6, %7, " \
        " %8, %9, %10, %11, %12, %13, %14, %15, " \
        " %16, %17, %18, %19, %20, %21, %22, %23, " \
        " %24, %25, %26, %27, %28, %29, %30, %31}, [%32];" \
        : "=r"((r)[0]),  "=r"((r)[1]),  "=r"((r)[2]),  "=r"((r)[3]), \
          "=r"((r)[4]),  "=r"((r)[5]),  "=r"((r)[6]),  "=r"((r)[7]), \
          "=r"((r)[8]),  "=r"((r)[9]),  "=r"((r)[10]), "=r"((r)[11]), \
          "=r"((r)[12]), "=r"((r)[13]), "=r"((r)[14]), "=r"((r)[15]), \
          "=r"((r)[16]), "=r"((r)[17]), "=r"((r)[18]), "=r"((r)[19]), \
          "=r"((r)[20]), "=r"((r)[21]), "=r"((r)[22]), "=r"((r)[23]), \
          "=r"((r)[24]), "=r"((r)[25]), "=r"((r)[26]), "=r"((r)[27]), \
          "=r"((r)[28]), "=r"((r)[29]), "=r"((r)[30]), "=r"((r)[31]) \
        : "r"(ta))

static constexpr uint64_t DESC_BASE_SW128 =
    (uint64_t(2) << 61) | (uint64_t(1) << 46) | (uint64_t(64) << 32) | (uint64_t(1) << 16);
#define MAKE_DESC(sa) (DESC_BASE_SW128 | ((uint64_t)((sa) >> 4) & 0x3FFF))
#define SMEM_SWIZZLE_128B(b)   ((b) ^ (((b) >> 3) & 0x70))

// idesc kind::f16, bf16 x bf16 -> f32, M=128, N=128
static constexpr uint32_t GEMM_IDESC =
    (1u << 4) | (1u << 7) | (1u << 10) | ((128u / 8) << 17) | ((128u / 16) << 24);

__device__ __forceinline__ void mma_f16_ss(uint32_t d, uint64_t a, uint64_t b,
                                           uint32_t idesc, uint32_t en) {
    asm volatile(
        "{\n\t.reg .pred p;\n\tsetp.ne.u32 p, %4, 0;\n\t"
        "tcgen05.mma.cta_group::1.kind::f16 [%0], %1, %2, %3, {%5, %5, %5, %5}, p;\n\t}"
        :: "r"(d), "l"(a), "l"(b), "r"(idesc), "r"(en), "r"(0u) : "memory");
}
#endif // USE_TCGEN05

// ---------------- pre-pass: transpose + split ----------------
// src [n][R][L] fp32 (L contiguous) -> dh/dl [n][L][R] bf16
__global__ __launch_bounds__(256) void transpose_split_kernel(
    const float* __restrict__ src, __nv_bfloat16* __restrict__ dh,
    __nv_bfloat16* __restrict__ dl, int R, int L) {
    __shared__ float tile[32][33];
    const int n = blockIdx.z;
    const float* s = src + (size_t)n * R * L;
    __nv_bfloat16* ph = dh + (size_t)n * R * L;
    __nv_bfloat16* pl = dl + (size_t)n * R * L;
    const int tx = threadIdx.x, ty = threadIdx.y;
    const int x = blockIdx.x * 32 + tx;     // L index
    const int y0 = blockIdx.y * 32;         // R base
    #pragma unroll
    for (int j = 0; j < 4; j++)
        tile[ty + j * 8][tx] = s[(size_t)(y0 + ty + j * 8) * L + x];
    __syncthreads();
    const int xo = y0 + tx;                 // R index (output inner)
    const int yb = blockIdx.x * 32;
    #pragma unroll
    for (int j = 0; j < 4; j++) {
        float v = tile[tx][ty + j * 8];
        __nv_bfloat16 h, l; split2(v, h, l);
        size_t o = (size_t)(yb + ty + j * 8) * R + xo;
        ph[o] = h; pl[o] = l;
    }
}

// elementwise split (V): float4 granularity
__global__ __launch_bounds__(256) void split_kernel(const float* __restrict__ src,
                                                    __nv_bfloat16* __restrict__ dh,
                                                    __nv_bfloat16* __restrict__ dl) {
    const size_t i = (size_t)blockIdx.x * blockDim.x + threadIdx.x;   // float4 index
    float4 v = ((const float4*)src)[i];
    __nv_bfloat16 h0, l0, h1, l1, h2, l2, h3, l3;
    split2(v.x, h0, l0); split2(v.y, h1, l1); split2(v.z, h2, l2); split2(v.w, h3, l3);
    __nv_bfloat162* oh = (__nv_bfloat162*)dh;
    __nv_bfloat162* ol = (__nv_bfloat162*)dl;
    oh[i * 2]     = __nv_bfloat162(h0, h1);
    oh[i * 2 + 1] = __nv_bfloat162(h2, h3);
    ol[i * 2]     = __nv_bfloat162(l0, l1);
    ol[i * 2 + 1] = __nv_bfloat162(l2, l3);
}

// ---------------- softmax: logits fp32 -> W bf16 hi/lo ----------------
__global__ __launch_bounds__(256) void softmax_kernel(const float* __restrict__ ratios) {
    const int warp = threadIdx.x >> 5;
    const int lane = threadIdx.x & 31;
    const int row  = blockIdx.x * 8 + warp;   // n*CC + c
    const int n    = row >> 9;
    const float r = ratios[n];
    const int vw  = min(WDIM, (int)floorf((float)WDIM * r + 0.5f));

    const float* p = g_logits + (size_t)row * TT;
    float v[32];
    float mx = -INFINITY;
    #pragma unroll
    for (int i = 0; i < 32; i++) {
        const int t = lane + i * 32;
        float x = p[t] * SCALE_F;
        if ((t & (WDIM - 1)) >= vw) x = -INFINITY;
        v[i] = x; mx = fmaxf(mx, x);
    }
    #pragma unroll
    for (int off = 16; off > 0; off >>= 1)
        mx = fmaxf(mx, __shfl_xor_sync(0xffffffffu, mx, off));
    float s = 0.0f;
    #pragma unroll
    for (int i = 0; i < 32; i++) { const float e = expf(v[i] - mx); v[i] = e; s += e; }
    #pragma unroll
    for (int off = 16; off > 0; off >>= 1)
        s += __shfl_xor_sync(0xffffffffu, s, off);
    const float inv = 1.0f / s;
    __nv_bfloat16* wh = g_Wh + (size_t)row * TT;
    __nv_bfloat16* wl = g_Wl + (size_t)row * TT;
    #pragma unroll
    for (int i = 0; i < 32; i++) {
        __nv_bfloat16 h, l; split2(v[i] * inv, h, l);
        wh[lane + i * 32] = h; wl[lane + i * 32] = l;
    }
}

// ---------------- GEMM: D[m][nn] = sum_k A[m][k]*B[nn][k] ----------------
// Tile 128x128, operands bf16 hi/lo k-major. tcgen05 path: ah*bh + ah*bl + al*bh,
// BK=64, double-buffered smem, TMEM accumulator. Fallback: fp32 SIMT 8x8 tiles.
#define SM_TMEM 0
#define SM_MBAR 8
#define SM_DATA 1024
#define TILE_B  16384
#define GEMM_SMEM (1024 + 8 * TILE_B)   // 132 KB

__global__ __launch_bounds__(256, 1)
void gemm_split_kernel(const __nv_bfloat16* __restrict__ Ah, const __nv_bfloat16* __restrict__ Al,
                       const __nv_bfloat16* __restrict__ Bh, const __nv_bfloat16* __restrict__ Bl,
                       float* __restrict__ C, int Kdim, int ldc,
                       size_t sA, size_t sB, size_t sC) {
    extern __shared__ char smem[];
    const int tid = threadIdx.x, wid = tid >> 5, lane = tid & 31;
    const int nz = blockIdx.z, m0 = blockIdx.y * 128, n0 = blockIdx.x * 128;

#if USE_TCGEN05
    const uint32_t sb = smem_to_u32(smem);
    const __nv_bfloat16* src[4];
    src[0] = Ah + nz * sA + (size_t)m0 * Kdim;
    src[1] = Al + nz * sA + (size_t)m0 * Kdim;
    src[2] = Bh + nz * sB + (size_t)n0 * Kdim;
    src[3] = Bl + nz * sB + (size_t)n0 * Kdim;

    if (wid == 0) { TCGEN05_ALLOC(sb + SM_TMEM, 128); TCGEN05_RELINQUISH(); }
    if (tid == 0) { MBARRIER_INIT(sb + SM_MBAR, 1); MBARRIER_INIT(sb + SM_MBAR + 8, 1); }
    __syncthreads();
    uint32_t tmem;
    asm volatile("ld.shared.b32 %0, [%1];" : "=r"(tmem) : "r"(sb + SM_TMEM));

    const int nch = Kdim >> 6;
    for (int ch = 0; ch < nch; ch++) {
        const int buf = ch & 1;
        if (ch >= 2) MBARRIER_WAIT_PARITY(sb + SM_MBAR + 8 * buf, ((ch - 2) >> 1) & 1);
        const int k0 = ch << 6;
        #pragma unroll
        for (int tg = 0; tg < 4; tg++) {
            char* tb = smem + SM_DATA + (size_t)(buf * 4 + tg) * TILE_B;
            const __nv_bfloat16* s = src[tg] + k0;
            #pragma unroll
            for (int i = 0; i < 4; i++) {
                const int idx = tid + i * 256;
                const int r = idx >> 3, c = idx & 7;
                uint4 u = *(const uint4*)(s + (size_t)r * Kdim + c * 8);
                *(uint4*)(tb + SMEM_SWIZZLE_128B((uint32_t)(r * 128 + c * 16))) = u;
            }
        }
        FENCE_PROXY_ASYNC();
        __syncthreads();
        if (wid == 0 && elect_one_pred()) {
            const uint64_t dAh = MAKE_DESC(sb + SM_DATA + (buf * 4 + 0) * TILE_B);
            const uint64_t dAl = MAKE_DESC(sb + SM_DATA + (buf * 4 + 1) * TILE_B);
            const uint64_t dBh = MAKE_DESC(sb + SM_DATA + (buf * 4 + 2) * TILE_B);
            const uint64_t dBl = MAKE_DESC(sb + SM_DATA + (buf * 4 + 3) * TILE_B);
            #pragma unroll
            for (int p = 0; p < 3; p++) {
                const uint64_t da = (p == 2) ? dAl : dAh;
                const uint64_t db = (p == 1) ? dBl : dBh;
                #pragma unroll
                for (int ks = 0; ks < 4; ks++) {
                    const uint32_t en = !(ch == 0 && p == 0 && ks == 0);
                    mma_f16_ss(tmem, da + ks * 2, db + ks * 2, GEMM_IDESC, en);
                }
            }
            TCGEN05_COMMIT(sb + SM_MBAR + 8 * buf);
        }
    }
    MBARRIER_WAIT_PARITY(sb + SM_MBAR + 8 * ((nch - 2) & 1), ((nch - 2) >> 1) & 1);
    MBARRIER_WAIT_PARITY(sb + SM_MBAR + 8 * ((nch - 1) & 1), ((nch - 1) >> 1) & 1);
    TCGEN05_FENCE_AFTER();

    if (wid < 4) {
        float* Crow = C + nz * sC + (size_t)(m0 + wid * 32 + lane) * ldc + n0;
        #pragma unroll
        for (int nb = 0; nb < 4; nb++) {
            uint32_t r[32];
            TCGEN05_LD_32X32B_X32(r, tmem + nb * 32);
            TCGEN05_WAIT_LD();
            #pragma unroll
            for (int j = 0; j < 8; j++) {
                float4 v;
                v.x = __uint_as_float(r[j * 4 + 0]);
                v.y = __uint_as_float(r[j * 4 + 1]);
                v.z = __uint_as_float(r[j * 4 + 2]);
                v.w = __uint_as_float(r[j * 4 + 3]);
                *(float4*)(Crow + nb * 32 + j * 4) = v;
            }
        }
        TCGEN05_FENCE_BEFORE();
    }
    __syncthreads();
    if (tid == 0) { MBARRIER_INVAL(sb + SM_MBAR); MBARRIER_INVAL(sb + SM_MBAR + 8); }
    __syncthreads();
    if (wid == 0) TCGEN05_DEALLOC(tmem, 128);

#else
    // ---- SIMT fallback: fp32 (hi+lo) 128x128 tile, 8x8/thread, f32x2 FMA ----
    float* As = (float*)smem;                       // [16][136]
    float* Bs = (float*)(smem + 16 * 136 * 4);      // [16][136]
    const __nv_bfloat16* pAh = Ah + nz * sA + (size_t)m0 * Kdim;
    const __nv_bfloat16* pAl = Al + nz * sA + (size_t)m0 * Kdim;
    const __nv_bfloat16* pBh = Bh + nz * sB + (size_t)n0 * Kdim;
    const __nv_bfloat16* pBl = Bl + nz * sB + (size_t)n0 * Kdim;

    const int tx = tid & 15;    // n-direction, 8 cols each
    const int ty = tid >> 4;    // m-direction, 8 rows each
    const int lr = tid >> 1;          // load row (0..127)
    const int lk = (tid & 1) * 8;     // load k offset (0 or 8)

    unsigned long long acc[8][4];
    #pragma unroll
    for (int i = 0; i < 8; i++)
        #pragma unroll
        for (int j = 0; j < 4; j++) acc[i][j] = 0ull;

    for (int k0 = 0; k0 < Kdim; k0 += 16) {
        {
            uint4 uh = *(const uint4*)(pAh + (size_t)lr * Kdim + k0 + lk);
            uint4 ul = *(const uint4*)(pAl + (size_t)lr * Kdim + k0 + lk);
            const uint32_t hh[4] = {uh.x, uh.y, uh.z, uh.w};
            const uint32_t ll[4] = {ul.x, ul.y, ul.z, ul.w};
            #pragma unroll
            for (int j = 0; j < 4; j++) {
                float2 h = bf2_to_f2(hh[j]), l = bf2_to_f2(ll[j]);
                As[(lk + j * 2 + 0) * 136 + lr] = h.x + l.x;
                As[(lk + j * 2 + 1) * 136 + lr] = h.y + l.y;
            }
        }
        {
            uint4 uh = *(const uint4*)(pBh + (size_t)lr * Kdim + k0 + lk);
            uint4 ul = *(const uint4*)(pBl + (size_t)lr * Kdim + k0 + lk);
            const uint32_t hh[4] = {uh.x, uh.y, uh.z, uh.w};
            const uint32_t ll[4] = {ul.x, ul.y, ul.z, ul.w};
            #pragma unroll
            for (int j = 0; j < 4; j++) {
                float2 h = bf2_to_f2(hh[j]), l = bf2_to_f2(ll[j]);
                Bs[(lk + j * 2 + 0) * 136 + lr] = h.x + l.x;
                Bs[(lk + j * 2 + 1) * 136 + lr] = h.y + l.y;
            }
        }
        __syncthreads();

        #pragma unroll
        for (int kk = 0; kk < 16; kk++) {
            float4 a0 = *(const float4*)&As[kk * 136 + ty * 8 + 0];
            float4 a1 = *(const float4*)&As[kk * 136 + ty * 8 + 4];
            unsigned long long b0 = *(const unsigned long long*)&Bs[kk * 136 + tx * 8 + 0];
            unsigned long long b1 = *(const unsigned long long*)&Bs[kk * 136 + tx * 8 + 2];
            unsigned long long b2 = *(const unsigned long long*)&Bs[kk * 136 + tx * 8 + 4];
            unsigned long long b3 = *(const unsigned long long*)&Bs[kk * 136 + tx * 8 + 6];
            float am[8] = {a0.x, a0.y, a0.z, a0.w, a1.x, a1.y, a1.z, a1.w};
            #pragma unroll
            for (int m = 0; m < 8; m++) {
                unsigned long long A2 = pack_dup(am[m]);
                FMA2(acc[m][0], A2, b0);
                FMA2(acc[m][1], A2, b1);
                FMA2(acc[m][2], A2, b2);
                FMA2(acc[m][3], A2, b3);
            }
        }
        __syncthreads();
    }

    #pragma unroll
    for (int m = 0; m < 8; m++) {
        float* Crow = C + nz * sC + (size_t)(m0 + ty * 8 + m) * ldc + n0 + tx * 8;
        #pragma unroll
        for (int p = 0; p < 4; p++)
            *(unsigned long long*)(Crow + p * 2) = acc[m][p];
    }
#endif
}

// ---------------- launch ----------------
extern "C" void kernel_launch(void* const* d_in, const int* in_sizes, int n_in,
                              void* d_out, int out_size) {
    const float* q      = (const float*)d_in[0];
    const float* k      = (const float*)d_in[1];
    const float* v      = (const float*)d_in[2];
    const float* ratios = (const float*)d_in[3];
    float* out = (float*)d_out;
    (void)in_sizes; (void)n_in; (void)out_size;

    float* lg; __nv_bfloat16 *qh, *ql, *kh, *kl, *vh, *vl, *wh, *wl;
    cudaGetSymbolAddress((void**)&lg, g_logits);
    cudaGetSymbolAddress((void**)&qh, g_Qth); cudaGetSymbolAddress((void**)&ql, g_Qtl);
    cudaGetSymbolAddress((void**)&kh, g_Kth); cudaGetSymbolAddress((void**)&kl, g_Ktl);
    cudaGetSymbolAddress((void**)&vh, g_Vh);  cudaGetSymbolAddress((void**)&vl, g_Vl);
    cudaGetSymbolAddress((void**)&wh, g_Wh);  cudaGetSymbolAddress((void**)&wl, g_Wl);

    cudaFuncSetAttribute(gemm_split_kernel,
                         cudaFuncAttributeMaxDynamicSharedMemorySize, GEMM_SMEM);

    // pre-pass: Qt[c][d], Kt[t][d], V split
    transpose_split_kernel<<<dim3(CC / 32, DD / 32, NB), dim3(32, 8)>>>(q, qh, ql, DD, CC);
    transpose_split_kernel<<<dim3(TT / 32, DD / 32, NB), dim3(32, 8)>>>(k, kh, kl, DD, TT);
    split_kernel<<<(NB * DD * TT / 4) / 256, 256>>>(v, vh, vl);

    // GEMM1: logits[c][t] = Qt[c][:] . Kt[t][:]   (K=512)
    gemm_split_kernel<<<dim3(TT / 128, CC / 128, NB), 256, GEMM_SMEM>>>(
        qh, ql, kh, kl, lg, DD, TT,
        (size_t)CC * DD, (size_t)TT * DD, (size_t)CC * TT);

    softmax_kernel<<<(NB * CC) / 8, 256>>>(ratios);

    // GEMM2: out[dd][c] = V[dd][:] . W[c][:]      (K=1024)
    gemm_split_kernel<<<dim3(CC / 128, DD / 128, NB), 256, GEMM_SMEM>>>(
        vh, vl, wh, wl, out, TT, CC,
        (size_t)DD * TT, (size_t)CC * TT, (size_t)DD * CC);
}

// round 8
// speedup vs baseline: 6.1917x; 1.2794x over previous
#include <cuda_runtime.h>
#include <cuda_bf16.h>
#include <cstdint>

// Shapes: query [64,512,512] (n,d,c); key/value [64,512,1024] (n,d,t); out [64,512,512]
#define NB 64
#define DD 512
#define CC 512
#define TT 1024
#define WDIM 128
#define SCALE_F 0.04419417382415922f   // 512^-0.5

// tcgen05 is arch-specific: only under sm_10xa passes.
#if defined(__CUDA_ARCH_FEAT_SM103_ALL) || defined(__CUDA_ARCH_FEAT_SM101_ALL) || \
    defined(__CUDA_ARCH_FEAT_SM100_ALL) || \
    (defined(__CUDA_ARCH_SPECIFIC__) && (__CUDA_ARCH_SPECIFIC__ >= 1000))
#define USE_TCGEN05 1
#else
#define USE_TCGEN05 0
#endif

// ---------------- scratch (device globals; no allocation) ----------------
__device__ float g_logits[(size_t)NB * CC * TT];                       // 134 MB
__device__ __align__(16) __nv_bfloat16 g_Qth[(size_t)NB * CC * DD];    // Qt[c][d] hi
__device__ __align__(16) __nv_bfloat16 g_Qtl[(size_t)NB * CC * DD];
__device__ __align__(16) __nv_bfloat16 g_Kth[(size_t)NB * TT * DD];    // Kt[t][d]
__device__ __align__(16) __nv_bfloat16 g_Ktl[(size_t)NB * TT * DD];
__device__ __align__(16) __nv_bfloat16 g_Vh [(size_t)NB * DD * TT];    // V[d][t]
__device__ __align__(16) __nv_bfloat16 g_Vl [(size_t)NB * DD * TT];
__device__ __align__(16) __nv_bfloat16 g_Wh [(size_t)NB * CC * TT];    // W[c][t]
__device__ __align__(16) __nv_bfloat16 g_Wl [(size_t)NB * CC * TT];

// ---------------- common helpers ----------------
__device__ __forceinline__ uint32_t smem_to_u32(const void* p) {
    uint32_t a;
    asm("{ .reg .u64 t; cvta.to.shared.u64 t, %1; cvt.u32.u64 %0, t; }" : "=r"(a) : "l"(p));
    return a;
}
__device__ __forceinline__ void split2(float x, __nv_bfloat16& h, __nv_bfloat16& l) {
    h = __float2bfloat16(x);
    l = __float2bfloat16(x - __bfloat162float(h));   // exact residual
}
#define FMA2(d, a, b) \
    asm("fma.rn.f32x2 %0, %1, %2, %0;" : "+l"(d) : "l"(a), "l"(b))
__device__ __forceinline__ unsigned long long pack_dup(float x) {
    unsigned long long r;
    unsigned int u = __float_as_uint(x);
    asm("mov.b64 %0, {%1, %2};" : "=l"(r) : "r"(u), "r"(u));
    return r;
}
__device__ __forceinline__ float2 bf2_to_f2(uint32_t u) {
    __nv_bfloat162 b = *reinterpret_cast<__nv_bfloat162*>(&u);
    return __bfloat1622float2(b);
}

#if USE_TCGEN05
// ---------------- PTX helpers (sm_103a-only pass) ----------------
__device__ __forceinline__ uint32_t elect_one_pred() {
    uint32_t pred;
    asm volatile("{\n\t.reg .pred p;\n\telect.sync _|p, 0xFFFFFFFF;\n\tselp.b32 %0, 1, 0, p;\n\t}" : "=r"(pred));
    return pred;
}
#define MBARRIER_INIT(a, c) \
    asm volatile("mbarrier.init.shared.b64 [%0], %1;" :: "r"((uint32_t)(a)), "r"((uint32_t)(c)) : "memory")
#define MBARRIER_INVAL(a) \
    asm volatile("mbarrier.inval.shared.b64 [%0];" :: "r"((uint32_t)(a)) : "memory")
#define MBARRIER_WAIT_PARITY(mbar_smem_addr, phase_parity) do { \
    uint32_t _mbar = (uint32_t)(mbar_smem_addr); \
    uint32_t _parity = (uint32_t)(phase_parity); \
    uint32_t _done; \
    asm volatile("{\n\t.reg .pred p;\n\t" \
        "mbarrier.try_wait.parity.acquire.cta.shared::cta.b64 p, [%1], %2;\n\t" \
        "selp.b32 %0, 1, 0, p;\n\t}" \
        : "=r"(_done) : "r"(_mbar), "r"(_parity) : "memory"); \
    if (!_done) { \
        asm volatile("{\n\t.reg .pred P1;\n\t" \
            "WAIT_LOOP_%=:\n\t" \
            "mbarrier.try_wait.parity.acquire.cta.shared::cta.b64 P1, [%0], %1, 0x989680;\n\t" \
            "@P1 bra.uni WAIT_DONE_%=;\n\t" \
            "bra.uni WAIT_LOOP_%=;\n\t" \
            "WAIT_DONE_%=:\n\t}" \
            :: "r"(_mbar), "r"(_parity) : "memory"); \
    } \
} while(0)
#define TCGEN05_ALLOC(sa, n) \
    asm volatile("tcgen05.alloc.cta_group::1.sync.aligned.shared::cta.b32 [%0], %1;" \
                 :: "r"((uint32_t)(sa)), "r"((uint32_t)(n)) : "memory")
#define TCGEN05_DEALLOC(t, n) \
    asm volatile("tcgen05.dealloc.cta_group::1.sync.aligned.b32 %0, %1;" :: "r"(t), "r"((uint32_t)(n)))
#define TCGEN05_RELINQUISH() \
    asm volatile("tcgen05.relinquish_alloc_permit.cta_group::1.sync.aligned;")
#define TCGEN05_COMMIT(a) \
    asm volatile("tcgen05.commit.cta_group::1.mbarrier::arrive::one.shared::cluster.b64 [%0];" \
                 :: "r"((uint32_t)(a)) : "memory")
#define TCGEN05_FENCE_AFTER()  asm volatile("tcgen05.fence::after_thread_sync;" ::: "memory")
#define TCGEN05_FENCE_BEFORE() asm volatile("tcgen05.fence::before_thread_sync;" ::: "memory")
#define TCGEN05_WAIT_LD()      asm volatile("tcgen05.wait::ld.sync.aligned;" ::: "memory")
#define FENCE_PROXY_ASYNC()    asm volatile("fence.proxy.async.shared::cta;" ::: "memory")
#define CP_ASYNC_16(dst, src) \
    asm volatile("cp.async.cg.shared.global [%0], [%1], 16;" :: "r"((uint32_t)(dst)), "l"(src) : "memory")
#define CP_ASYNC_COMMIT() asm volatile("cp.async.commit_group;" ::: "memory")
#define CP_ASYNC_WAIT2()  asm volatile("cp.async.wait_group 2;" ::: "memory")

#define TCGEN05_LD_32X32B_X32(r, ta) \
    asm volatile( \
        "tcgen05.ld.sync.aligned.32x32b.x32.b32 " \
        "{%0, %1, %2, %3, %4, %5, %6, %7, " \
        " %8, %9, %10, %11, %12, %13, %14, %15, " \
        " %16, %17, %18, %19, %20, %21, %22, %23, " \
        " %24, %25, %26, %27, %28, %29, %30, %31}, [%32];" \
        : "=r"((r)[0]),  "=r"((r)[1]),  "=r"((r)[2]),  "=r"((r)[3]), \
          "=r"((r)[4]),  "=r"((r)[5]),  "=r"((r)[6]),  "=r"((r)[7]), \
          "=r"((r)[8]),  "=r"((r)[9]),  "=r"((r)[10]), "=r"((r)[11]), \
          "=r"((r)[12]), "=r"((r)[13]), "=r"((r)[14]), "=r"((r)[15]), \
          "=r"((r)[16]), "=r"((r)[17]), "=r"((r)[18]), "=r"((r)[19]), \
          "=r"((r)[20]), "=r"((r)[21]), "=r"((r)[22]), "=r"((r)[23]), \
          "=r"((r)[24]), "=r"((r)[25]), "=r"((r)[26]), "=r"((r)[27]), \
          "=r"((r)[28]), "=r"((r)[29]), "=r"((r)[30]), "=r"((r)[31]) \
        : "r"(ta))

static constexpr uint64_t DESC_BASE_SW128 =
    (uint64_t(2) << 61) | (uint64_t(1) << 46) | (uint64_t(64) << 32) | (uint64_t(1) << 16);
#define MAKE_DESC(sa) (DESC_BASE_SW128 | ((uint64_t)((sa) >> 4) & 0x3FFF))
#define SMEM_SWIZZLE_128B(b)   ((b) ^ (((b) >> 3) & 0x70))

// idesc kind::f16, bf16 x bf16 -> f32, M=128, N=128
static constexpr uint32_t GEMM_IDESC =
    (1u << 4) | (1u << 7) | (1u << 10) | ((128u / 8) << 17) | ((128u / 16) << 24);

__device__ __forceinline__ void mma_f16_ss(uint32_t d, uint64_t a, uint64_t b,
                                           uint32_t idesc, uint32_t en) {
    asm volatile(
        "{\n\t.reg .pred p;\n\tsetp.ne.u32 p, %4, 0;\n\t"
        "tcgen05.mma.cta_group::1.kind::f16 [%0], %1, %2, %3, {%5, %5, %5, %5}, p;\n\t}"
        :: "r"(d), "l"(a), "l"(b), "r"(idesc), "r"(en), "r"(0u) : "memory");
}
#endif // USE_TCGEN05

// ---------------- pre-pass: transpose + split ----------------
// src [n][R][L] fp32 (L contiguous) -> dh/dl [n][L][R] bf16 (bf162 stores)
__global__ __launch_bounds__(256) void transpose_split_kernel(
    const float* __restrict__ src, __nv_bfloat16* __restrict__ dh,
    __nv_bfloat16* __restrict__ dl, int R, int L) {
    __shared__ float tile[32][33];
    const int n = blockIdx.z;
    const float* s = src + (size_t)n * R * L;
    __nv_bfloat16* ph = dh + (size_t)n * R * L;
    __nv_bfloat16* pl = dl + (size_t)n * R * L;
    const int tx = threadIdx.x, ty = threadIdx.y;
    const int x  = blockIdx.x * 32 + tx;    // L index
    const int y0 = blockIdx.y * 32;         // R base
    #pragma unroll
    for (int j = 0; j < 4; j++)
        tile[ty + j * 8][tx] = s[(size_t)(y0 + ty + j * 8) * L + x];
    __syncthreads();
    const int yb  = blockIdx.x * 32;        // L base
    const int tid = ty * 32 + tx;
    #pragma unroll
    for (int it = 0; it < 2; it++) {
        const int wi = tid + it * 256;      // 0..511
        const int yo = wi >> 4;             // L col 0..31
        const int p  = wi & 15;             // R pair 0..15
        float v0 = tile[2 * p + 0][yo];
        float v1 = tile[2 * p + 1][yo];
        __nv_bfloat16 h0, l0, h1, l1;
        split2(v0, h0, l0); split2(v1, h1, l1);
        const size_t o = ((size_t)(yb + yo) * R + y0 + 2 * p) >> 1;
        ((__nv_bfloat162*)ph)[o] = __nv_bfloat162(h0, h1);
        ((__nv_bfloat162*)pl)[o] = __nv_bfloat162(l0, l1);
    }
}

// elementwise split (V): float4 granularity
__global__ __launch_bounds__(256) void split_kernel(const float* __restrict__ src,
                                                    __nv_bfloat16* __restrict__ dh,
                                                    __nv_bfloat16* __restrict__ dl) {
    const size_t i = (size_t)blockIdx.x * blockDim.x + threadIdx.x;   // float4 index
    float4 v = ((const float4*)src)[i];
    __nv_bfloat16 h0, l0, h1, l1, h2, l2, h3, l3;
    split2(v.x, h0, l0); split2(v.y, h1, l1); split2(v.z, h2, l2); split2(v.w, h3, l3);
    __nv_bfloat162* oh = (__nv_bfloat162*)dh;
    __nv_bfloat162* ol = (__nv_bfloat162*)dl;
    oh[i * 2]     = __nv_bfloat162(h0, h1);
    oh[i * 2 + 1] = __nv_bfloat162(h2, h3);
    ol[i * 2]     = __nv_bfloat162(l0, l1);
    ol[i * 2 + 1] = __nv_bfloat162(l2, l3);
}

// ---------------- softmax: logits fp32 -> W bf16 hi/lo ----------------
__global__ __launch_bounds__(256) void softmax_kernel(const float* __restrict__ ratios) {
    const int warp = threadIdx.x >> 5;
    const int lane = threadIdx.x & 31;
    const int row  = blockIdx.x * 8 + warp;   // n*CC + c
    const int n    = row >> 9;
    const float r = ratios[n];
    const int vw  = min(WDIM, (int)floorf((float)WDIM * r + 0.5f));

    const float* p = g_logits + (size_t)row * TT;
    float v[32];
    float mx = -INFINITY;
    #pragma unroll
    for (int i = 0; i < 32; i++) {
        const int t = lane + i * 32;
        float x = p[t] * SCALE_F;
        if ((t & (WDIM - 1)) >= vw) x = -INFINITY;
        v[i] = x; mx = fmaxf(mx, x);
    }
    #pragma unroll
    for (int off = 16; off > 0; off >>= 1)
        mx = fmaxf(mx, __shfl_xor_sync(0xffffffffu, mx, off));
    float s = 0.0f;
    #pragma unroll
    for (int i = 0; i < 32; i++) { const float e = expf(v[i] - mx); v[i] = e; s += e; }
    #pragma unroll
    for (int off = 16; off > 0; off >>= 1)
        s += __shfl_xor_sync(0xffffffffu, s, off);
    const float inv = 1.0f / s;
    __nv_bfloat16* wh = g_Wh + (size_t)row * TT;
    __nv_bfloat16* wl = g_Wl + (size_t)row * TT;
    #pragma unroll
    for (int i = 0; i < 32; i++) {
        __nv_bfloat16 h, l; split2(v[i] * inv, h, l);
        wh[lane + i * 32] = h; wl[lane + i * 32] = l;
    }
}

// ---------------- GEMM: D[m][nn] = sum_k A[m][k]*B[nn][k] ----------------
// tcgen05: 128x128 tile, BK=64 chunks, 3-stage cp.async ring, TMEM accumulator,
// 3 MMA passes (ah*bh + ah*bl + al*bh). Fallback: fp32 SIMT 8x8 tiles.
#define SM_TMEM 0
#define SM_MBAR 8
#define SM_DATA 1024
#define TILE_B  16384
#define STAGES  3
#define CHUNK_B (4 * TILE_B)
#define GEMM_SMEM (1024 + STAGES * CHUNK_B)   // 197632 B

__global__ __launch_bounds__(256, 1)
void gemm_split_kernel(const __nv_bfloat16* __restrict__ Ah, const __nv_bfloat16* __restrict__ Al,
                       const __nv_bfloat16* __restrict__ Bh, const __nv_bfloat16* __restrict__ Bl,
                       float* __restrict__ C, int Kdim, int ldc,
                       size_t sA, size_t sB, size_t sC) {
    extern __shared__ char smem[];
    const int tid = threadIdx.x, wid = tid >> 5, lane = tid & 31;
    const int nz = blockIdx.z, m0 = blockIdx.y * 128, n0 = blockIdx.x * 128;

#if USE_TCGEN05
    const uint32_t sb = smem_to_u32(smem);
    const __nv_bfloat16* src[4];
    src[0] = Ah + nz * sA + (size_t)m0 * Kdim;
    src[1] = Al + nz * sA + (size_t)m0 * Kdim;
    src[2] = Bh + nz * sB + (size_t)n0 * Kdim;
    src[3] = Bl + nz * sB + (size_t)n0 * Kdim;

    if (wid == 0) { TCGEN05_ALLOC(sb + SM_TMEM, 128); TCGEN05_RELINQUISH(); }
    if (tid == 0) {
        #pragma unroll
        for (int s = 0; s < STAGES; s++) MBARRIER_INIT(sb + SM_MBAR + 8 * s, 1);
    }
    __syncthreads();
    uint32_t tmem;
    asm volatile("ld.shared.b32 %0, [%1];" : "=r"(tmem) : "r"(sb + SM_TMEM));

    const int r_ = tid >> 3, c_ = tid & 7;            // fill coords
    const int nch = Kdim >> 6;

    // fill one BK=64 chunk (4 tiles x 16KB) into stage ch%STAGES via cp.async
    auto fill = [&](int ch) {
        const int s  = ch % STAGES;
        const int k0 = ch << 6;
        #pragma unroll
        for (int tg = 0; tg < 4; tg++) {
            const uint32_t tb = sb + SM_DATA + (uint32_t)(s * 4 + tg) * TILE_B;
            const __nv_bfloat16* gs = src[tg] + k0;
            #pragma unroll
            for (int i = 0; i < 4; i++) {
                const int r = r_ + i * 32;
                const uint32_t dst = tb + SMEM_SWIZZLE_128B((uint32_t)(r * 128 + c_ * 16));
                CP_ASYNC_16(dst, (const void*)(gs + (size_t)r * Kdim + c_ * 8));
            }
        }
        CP_ASYNC_COMMIT();
    };

    fill(0);
    if (nch > 1) fill(1);

    for (int ch = 0; ch < nch; ch++) {
        if (ch + 2 < nch) {
            // stage (ch+2)%3 last held chunk ch-1 -> wait for its MMA commit
            if (ch >= 1)
                MBARRIER_WAIT_PARITY(sb + SM_MBAR + 8 * ((ch - 1) % STAGES),
                                     ((ch - 1) / STAGES) & 1);
            fill(ch + 2);
        } else {
            CP_ASYNC_COMMIT();   // empty group keeps wait_group accounting uniform
        }
        CP_ASYNC_WAIT2();        // fill(ch) complete
        FENCE_PROXY_ASYNC();     // order cp.async smem writes vs tcgen05 async-proxy reads
        __syncthreads();
        if (wid == 0 && elect_one_pred()) {
            const int s = ch % STAGES;
            const uint64_t dAh = MAKE_DESC(sb + SM_DATA + (s * 4 + 0) * TILE_B);
            const uint64_t dAl = MAKE_DESC(sb + SM_DATA + (s * 4 + 1) * TILE_B);
            const uint64_t dBh = MAKE_DESC(sb + SM_DATA + (s * 4 + 2) * TILE_B);
            const uint64_t dBl = MAKE_DESC(sb + SM_DATA + (s * 4 + 3) * TILE_B);
            #pragma unroll
            for (int p = 0; p < 3; p++) {
                const uint64_t da = (p == 2) ? dAl : dAh;
                const uint64_t db = (p == 1) ? dBl : dBh;
                #pragma unroll
                for (int ks = 0; ks < 4; ks++) {
                    const uint32_t en = !(ch == 0 && p == 0 && ks == 0);
                    mma_f16_ss(tmem, da + ks * 2, db + ks * 2, GEMM_IDESC, en);
                }
            }
            TCGEN05_COMMIT(sb + SM_MBAR + 8 * s);
        }
    }
    // last chunk's commit implies all prior MMAs complete
    MBARRIER_WAIT_PARITY(sb + SM_MBAR + 8 * ((nch - 1) % STAGES), ((nch - 1) / STAGES) & 1);
    TCGEN05_FENCE_AFTER();

    if (wid < 4) {
        float* Crow = C + nz * sC + (size_t)(m0 + wid * 32 + lane) * ldc + n0;
        #pragma unroll
        for (int nb = 0; nb < 4; nb++) {
            uint32_t r[32];
            TCGEN05_LD_32X32B_X32(r, tmem + nb * 32);
            TCGEN05_WAIT_LD();
            #pragma unroll
            for (int j = 0; j < 8; j++) {
                float4 v;
                v.x = __uint_as_float(r[j * 4 + 0]);
                v.y = __uint_as_float(r[j * 4 + 1]);
                v.z = __uint_as_float(r[j * 4 + 2]);
                v.w = __uint_as_float(r[j * 4 + 3]);
                *(float4*)(Crow + nb * 32 + j * 4) = v;
            }
        }
        TCGEN05_FENCE_BEFORE();
    }
    __syncthreads();
    if (tid == 0) {
        #pragma unroll
        for (int s = 0; s < STAGES; s++) MBARRIER_INVAL(sb + SM_MBAR + 8 * s);
    }
    __syncthreads();
    if (wid == 0) TCGEN05_DEALLOC(tmem, 128);

#else
    // ---- SIMT fallback: fp32 (hi+lo) 128x128 tile, 8x8/thread, f32x2 FMA ----
    float* As = (float*)smem;                       // [16][136]
    float* Bs = (float*)(smem + 16 * 136 * 4);      // [16][136]
    const __nv_bfloat16* pAh = Ah + nz * sA + (size_t)m0 * Kdim;
    const __nv_bfloat16* pAl = Al + nz * sA + (size_t)m0 * Kdim;
    const __nv_bfloat16* pBh = Bh + nz * sB + (size_t)n0 * Kdim;
    const __nv_bfloat16* pBl = Bl + nz * sB + (size_t)n0 * Kdim;

    const int tx = tid & 15;
    const int ty = tid >> 4;
    const int lr = tid >> 1;
    const int lk = (tid & 1) * 8;

    unsigned long long acc[8][4];
    #pragma unroll
    for (int i = 0; i < 8; i++)
        #pragma unroll
        for (int j = 0; j < 4; j++) acc[i][j] = 0ull;

    for (int k0 = 0; k0 < Kdim; k0 += 16) {
        {
            uint4 uh = *(const uint4*)(pAh + (size_t)lr * Kdim + k0 + lk);
            uint4 ul = *(const uint4*)(pAl + (size_t)lr * Kdim + k0 + lk);
            const uint32_t hh[4] = {uh.x, uh.y, uh.z, uh.w};
            const uint32_t ll[4] = {ul.x, ul.y, ul.z, ul.w};
            #pragma unroll
            for (int j = 0; j < 4; j++) {
                float2 h = bf2_to_f2(hh[j]), l = bf2_to_f2(ll[j]);
                As[(lk + j * 2 + 0) * 136 + lr] = h.x + l.x;
                As[(lk + j * 2 + 1) * 136 + lr] = h.y + l.y;
            }
        }
        {
            uint4 uh = *(const uint4*)(pBh + (size_t)lr * Kdim + k0 + lk);
            uint4 ul = *(const uint4*)(pBl + (size_t)lr * Kdim + k0 + lk);
            const uint32_t hh[4] = {uh.x, uh.y, uh.z, uh.w};
            const uint32_t ll[4] = {ul.x, ul.y, ul.z, ul.w};
            #pragma unroll
            for (int j = 0; j < 4; j++) {
                float2 h = bf2_to_f2(hh[j]), l = bf2_to_f2(ll[j]);
                Bs[(lk + j * 2 + 0) * 136 + lr] = h.x + l.x;
                Bs[(lk + j * 2 + 1) * 136 + lr] = h.y + l.y;
            }
        }
        __syncthreads();

        #pragma unroll
        for (int kk = 0; kk < 16; kk++) {
            float4 a0 = *(const float4*)&As[kk * 136 + ty * 8 + 0];
            float4 a1 = *(const float4*)&As[kk * 136 + ty * 8 + 4];
            unsigned long long b0 = *(const unsigned long long*)&Bs[kk * 136 + tx * 8 + 0];
            unsigned long long b1 = *(const unsigned long long*)&Bs[kk * 136 + tx * 8 + 2];
            unsigned long long b2 = *(const unsigned long long*)&Bs[kk * 136 + tx * 8 + 4];
            unsigned long long b3 = *(const unsigned long long*)&Bs[kk * 136 + tx * 8 + 6];
            float am[8] = {a0.x, a0.y, a0.z, a0.w, a1.x, a1.y, a1.z, a1.w};
            #pragma unroll
            for (int m = 0; m < 8; m++) {
                unsigned long long A2 = pack_dup(am[m]);
                FMA2(acc[m][0], A2, b0);
                FMA2(acc[m][1], A2, b1);
                FMA2(acc[m][2], A2, b2);
                FMA2(acc[m][3], A2, b3);
            }
        }
        __syncthreads();
    }

    #pragma unroll
    for (int m = 0; m < 8; m++) {
        float* Crow = C + nz * sC + (size_t)(m0 + ty * 8 + m) * ldc + n0 + tx * 8;
        #pragma unroll
        for (int p = 0; p < 4; p++)
            *(unsigned long long*)(Crow + p * 2) = acc[m][p];
    }
#endif
}

// ---------------- launch ----------------
extern "C" void kernel_launch(void* const* d_in, const int* in_sizes, int n_in,
                              void* d_out, int out_size) {
    const float* q      = (const float*)d_in[0];
    const float* k      = (const float*)d_in[1];
    const float* v      = (const float*)d_in[2];
    const float* ratios = (const float*)d_in[3];
    float* out = (float*)d_out;
    (void)in_sizes; (void)n_in; (void)out_size;

    float* lg; __nv_bfloat16 *qh, *ql, *kh, *kl, *vh, *vl, *wh, *wl;
    cudaGetSymbolAddress((void**)&lg, g_logits);
    cudaGetSymbolAddress((void**)&qh, g_Qth); cudaGetSymbolAddress((void**)&ql, g_Qtl);
    cudaGetSymbolAddress((void**)&kh, g_Kth); cudaGetSymbolAddress((void**)&kl, g_Ktl);
    cudaGetSymbolAddress((void**)&vh, g_Vh);  cudaGetSymbolAddress((void**)&vl, g_Vl);
    cudaGetSymbolAddress((void**)&wh, g_Wh);  cudaGetSymbolAddress((void**)&wl, g_Wl);

    cudaFuncSetAttribute(gemm_split_kernel,
                         cudaFuncAttributeMaxDynamicSharedMemorySize, GEMM_SMEM);

    // pre-pass: Qt[c][d], Kt[t][d], V split
    transpose_split_kernel<<<dim3(CC / 32, DD / 32, NB), dim3(32, 8)>>>(q, qh, ql, DD, CC);
    transpose_split_kernel<<<dim3(TT / 32, DD / 32, NB), dim3(32, 8)>>>(k, kh, kl, DD, TT);
    split_kernel<<<(NB * DD * TT / 4) / 256, 256>>>(v, vh, vl);

    // GEMM1: logits[c][t] = Qt[c][:] . Kt[t][:]   (K=512)
    gemm_split_kernel<<<dim3(TT / 128, CC / 128, NB), 256, GEMM_SMEM>>>(
        qh, ql, kh, kl, lg, DD, TT,
        (size_t)CC * DD, (size_t)TT * DD, (size_t)CC * TT);

    softmax_kernel<<<(NB * CC) / 8, 256>>>(ratios);

    // GEMM2: out[dd][c] = V[dd][:] . W[c][:]      (K=1024)
    gemm_split_kernel<<<dim3(CC / 128, DD / 128, NB), 256, GEMM_SMEM>>>(
        vh, vl, wh, wl, out, TT, CC,
        (size_t)DD * TT, (size_t)CC * TT, (size_t)DD * CC);
}

// round 12
// speedup vs baseline: 6.7231x; 1.0858x over previous
#include <cuda_runtime.h>
#include <cuda_bf16.h>
#include <cstdint>

// Shapes: query [64,512,512] (n,d,c); key/value [64,512,1024] (n,d,t); out [64,512,512]
#define NB 64
#define DD 512
#define CC 512
#define TT 1024
#define WDIM 128
#define SCALE_F 0.04419417382415922f   // 512^-0.5

// tcgen05 is arch-specific: only under sm_10xa passes.
#if defined(__CUDA_ARCH_FEAT_SM103_ALL) || defined(__CUDA_ARCH_FEAT_SM101_ALL) || \
    defined(__CUDA_ARCH_FEAT_SM100_ALL) || \
    (defined(__CUDA_ARCH_SPECIFIC__) && (__CUDA_ARCH_SPECIFIC__ >= 1000))
#define USE_TCGEN05 1
#else
#define USE_TCGEN05 0
#endif

// ---------------- scratch (device globals; no allocation) ----------------
__device__ float g_logits[(size_t)NB * CC * TT];                       // 134 MB
__device__ __align__(16) __nv_bfloat16 g_Qth[(size_t)NB * CC * DD];    // Qt[c][d] hi
__device__ __align__(16) __nv_bfloat16 g_Qtl[(size_t)NB * CC * DD];
__device__ __align__(16) __nv_bfloat16 g_Kth[(size_t)NB * TT * DD];    // Kt[t][d]
__device__ __align__(16) __nv_bfloat16 g_Ktl[(size_t)NB * TT * DD];
__device__ __align__(16) __nv_bfloat16 g_Vh [(size_t)NB * DD * TT];    // V[d][t]
__device__ __align__(16) __nv_bfloat16 g_Vl [(size_t)NB * DD * TT];
__device__ __align__(16) __nv_bfloat16 g_Wh [(size_t)NB * CC * TT];    // W[c][t]
__device__ __align__(16) __nv_bfloat16 g_Wl [(size_t)NB * CC * TT];

// ---------------- common helpers ----------------
__device__ __forceinline__ uint32_t smem_to_u32(const void* p) {
    uint32_t a;
    asm("{ .reg .u64 t; cvta.to.shared.u64 t, %1; cvt.u32.u64 %0, t; }" : "=r"(a) : "l"(p));
    return a;
}
__device__ __forceinline__ void split2(float x, __nv_bfloat16& h, __nv_bfloat16& l) {
    h = __float2bfloat16(x);
    l = __float2bfloat16(x - __bfloat162float(h));   // exact residual
}
#define FMA2(d, a, b) \
    asm("fma.rn.f32x2 %0, %1, %2, %0;" : "+l"(d) : "l"(a), "l"(b))
__device__ __forceinline__ unsigned long long pack_dup(float x) {
    unsigned long long r;
    unsigned int u = __float_as_uint(x);
    asm("mov.b64 %0, {%1, %2};" : "=l"(r) : "r"(u), "r"(u));
    return r;
}
__device__ __forceinline__ float2 bf2_to_f2(uint32_t u) {
    __nv_bfloat162 b = *reinterpret_cast<__nv_bfloat162*>(&u);
    return __bfloat1622float2(b);
}

#if USE_TCGEN05
// ---------------- PTX helpers (sm_103a-only pass) ----------------
__device__ __forceinline__ uint32_t elect_one_pred() {
    uint32_t pred;
    asm volatile("{\n\t.reg .pred p;\n\telect.sync _|p, 0xFFFFFFFF;\n\tselp.b32 %0, 1, 0, p;\n\t}" : "=r"(pred));
    return pred;
}
#define MBARRIER_INIT(a, c) \
    asm volatile("mbarrier.init.shared.b64 [%0], %1;" :: "r"((uint32_t)(a)), "r"((uint32_t)(c)) : "memory")
#define MBARRIER_INVAL(a) \
    asm volatile("mbarrier.inval.shared.b64 [%0];" :: "r"((uint32_t)(a)) : "memory")
#define MBARRIER_WAIT_PARITY(mbar_smem_addr, phase_parity) do { \
    uint32_t _mbar = (uint32_t)(mbar_smem_addr); \
    uint32_t _parity = (uint32_t)(phase_parity); \
    uint32_t _done; \
    asm volatile("{\n\t.reg .pred p;\n\t" \
        "mbarrier.try_wait.parity.acquire.cta.shared::cta.b64 p, [%1], %2;\n\t" \
        "selp.b32 %0, 1, 0, p;\n\t}" \
        : "=r"(_done) : "r"(_mbar), "r"(_parity) : "memory"); \
    if (!_done) { \
        asm volatile("{\n\t.reg .pred P1;\n\t" \
            "WAIT_LOOP_%=:\n\t" \
            "mbarrier.try_wait.parity.acquire.cta.shared::cta.b64 P1, [%0], %1, 0x989680;\n\t" \
            "@P1 bra.uni WAIT_DONE_%=;\n\t" \
            "bra.uni WAIT_LOOP_%=;\n\t" \
            "WAIT_DONE_%=:\n\t}" \
            :: "r"(_mbar), "r"(_parity) : "memory"); \
    } \
} while(0)
#define TCGEN05_ALLOC(sa, n) \
    asm volatile("tcgen05.alloc.cta_group::1.sync.aligned.shared::cta.b32 [%0], %1;" \
                 :: "r"((uint32_t)(sa)), "r"((uint32_t)(n)) : "memory")
#define TCGEN05_DEALLOC(t, n) \
    asm volatile("tcgen05.dealloc.cta_group::1.sync.aligned.b32 %0, %1;" :: "r"(t), "r"((uint32_t)(n)))
#define TCGEN05_RELINQUISH() \
    asm volatile("tcgen05.relinquish_alloc_permit.cta_group::1.sync.aligned;")
#define TCGEN05_COMMIT(a) \
    asm volatile("tcgen05.commit.cta_group::1.mbarrier::arrive::one.shared::cluster.b64 [%0];" \
                 :: "r"((uint32_t)(a)) : "memory")
#define TCGEN05_FENCE_AFTER()  asm volatile("tcgen05.fence::after_thread_sync;" ::: "memory")
#define TCGEN05_FENCE_BEFORE() asm volatile("tcgen05.fence::before_thread_sync;" ::: "memory")
#define TCGEN05_WAIT_LD()      asm volatile("tcgen05.wait::ld.sync.aligned;" ::: "memory")
#define FENCE_PROXY_ASYNC()    asm volatile("fence.proxy.async.shared::cta;" ::: "memory")
#define CP_ASYNC_16(dst, src) \
    asm volatile("cp.async.cg.shared.global [%0], [%1], 16;" :: "r"((uint32_t)(dst)), "l"(src) : "memory")
// completion-gated arrival: fires one arrival on [bar] when all prior cp.async
// of this thread have completed. .noinc => expected count fixed at init (128).
#define CP_ASYNC_MBAR_ARRIVE(bar) \
    asm volatile("cp.async.mbarrier.arrive.noinc.shared.b64 [%0];" :: "r"((uint32_t)(bar)) : "memory")

#define TCGEN05_LD_32X32B_X32(r, ta) \
    asm volatile( \
        "tcgen05.ld.sync.aligned.32x32b.x32.b32 " \
        "{%0, %1, %2, %3, %4, %5, %6, %7, " \
        " %8, %9, %10, %11, %12, %13, %14, %15, " \
        " %16, %17, %18, %19, %20, %21, %22, %23, " \
        " %24, %25, %26, %27, %28, %29, %30, %31}, [%32];" \
        : "=r"((r)[0]),  "=r"((r)[1]),  "=r"((r)[2]),  "=r"((r)[3]), \
          "=r"((r)[4]),  "=r"((r)[5]),  "=r"((r)[6]),  "=r"((r)[7]), \
          "=r"((r)[8]),  "=r"((r)[9]),  "=r"((r)[10]), "=r"((r)[11]), \
          "=r"((r)[12]), "=r"((r)[13]), "=r"((r)[14]), "=r"((r)[15]), \
          "=r"((r)[16]), "=r"((r)[17]), "=r"((r)[18]), "=r"((r)[19]), \
          "=r"((r)[20]), "=r"((r)[21]), "=r"((r)[22]), "=r"((r)[23]), \
          "=r"((r)[24]), "=r"((r)[25]), "=r"((r)[26]), "=r"((r)[27]), \
          "=r"((r)[28]), "=r"((r)[29]), "=r"((r)[30]), "=r"((r)[31]) \
        : "r"(ta))

static constexpr uint64_t DESC_BASE_SW128 =
    (uint64_t(2) << 61) | (uint64_t(1) << 46) | (uint64_t(64) << 32) | (uint64_t(1) << 16);
#define MAKE_DESC(sa) (DESC_BASE_SW128 | ((uint64_t)((sa) >> 4) & 0x3FFF))
#define SMEM_SWIZZLE_128B(b)   ((b) ^ (((b) >> 3) & 0x70))

// idesc kind::f16, bf16 x bf16 -> f32, M=128, N=128
static constexpr uint32_t GEMM_IDESC =
    (1u << 4) | (1u << 7) | (1u << 10) | ((128u / 8) << 17) | ((128u / 16) << 24);

__device__ __forceinline__ void mma_f16_ss(uint32_t d, uint64_t a, uint64_t b,
                                           uint32_t idesc, uint32_t en) {
    asm volatile(
        "{\n\t.reg .pred p;\n\tsetp.ne.u32 p, %4, 0;\n\t"
        "tcgen05.mma.cta_group::1.kind::f16 [%0], %1, %2, %3, {%5, %5, %5, %5}, p;\n\t}"
        :: "r"(d), "l"(a), "l"(b), "r"(idesc), "r"(en), "r"(0u) : "memory");
}
#endif // USE_TCGEN05

// ---------------- pre-pass: transpose + split ----------------
// src [n][R][L] fp32 (L contiguous) -> dh/dl [n][L][R] bf16 (bf162 stores)
__global__ __launch_bounds__(256) void transpose_split_kernel(
    const float* __restrict__ src, __nv_bfloat16* __restrict__ dh,
    __nv_bfloat16* __restrict__ dl, int R, int L) {
    __shared__ float tile[32][33];
    const int n = blockIdx.z;
    const float* s = src + (size_t)n * R * L;
    __nv_bfloat16* ph = dh + (size_t)n * R * L;
    __nv_bfloat16* pl = dl + (size_t)n * R * L;
    const int tx = threadIdx.x, ty = threadIdx.y;
    const int x  = blockIdx.x * 32 + tx;    // L index
    const int y0 = blockIdx.y * 32;         // R base
    #pragma unroll
    for (int j = 0; j < 4; j++)
        tile[ty + j * 8][tx] = s[(size_t)(y0 + ty + j * 8) * L + x];
    __syncthreads();
    const int yb  = blockIdx.x * 32;        // L base
    const int tid = ty * 32 + tx;
    #pragma unroll
    for (int it = 0; it < 2; it++) {
        const int wi = tid + it * 256;      // 0..511
        const int yo = wi >> 4;             // L col 0..31
        const int p  = wi & 15;             // R pair 0..15
        float v0 = tile[2 * p + 0][yo];
        float v1 = tile[2 * p + 1][yo];
        __nv_bfloat16 h0, l0, h1, l1;
        split2(v0, h0, l0); split2(v1, h1, l1);
        const size_t o = ((size_t)(yb + yo) * R + y0 + 2 * p) >> 1;
        ((__nv_bfloat162*)ph)[o] = __nv_bfloat162(h0, h1);
        ((__nv_bfloat162*)pl)[o] = __nv_bfloat162(l0, l1);
    }
}

// elementwise split (V): float4 granularity
__global__ __launch_bounds__(256) void split_kernel(const float* __restrict__ src,
                                                    __nv_bfloat16* __restrict__ dh,
                                                    __nv_bfloat16* __restrict__ dl) {
    const size_t i = (size_t)blockIdx.x * blockDim.x + threadIdx.x;   // float4 index
    float4 v = ((const float4*)src)[i];
    __nv_bfloat16 h0, l0, h1, l1, h2, l2, h3, l3;
    split2(v.x, h0, l0); split2(v.y, h1, l1); split2(v.z, h2, l2); split2(v.w, h3, l3);
    __nv_bfloat162* oh = (__nv_bfloat162*)dh;
    __nv_bfloat162* ol = (__nv_bfloat162*)dl;
    oh[i * 2]     = __nv_bfloat162(h0, h1);
    oh[i * 2 + 1] = __nv_bfloat162(h2, h3);
    ol[i * 2]     = __nv_bfloat162(l0, l1);
    ol[i * 2 + 1] = __nv_bfloat162(l2, l3);
}

// ---------------- softmax: logits fp32 -> W bf16 hi/lo ----------------
__global__ __launch_bounds__(256) void softmax_kernel(const float* __restrict__ ratios) {
    const int warp = threadIdx.x >> 5;
    const int lane = threadIdx.x & 31;
    const int row  = blockIdx.x * 8 + warp;   // n*CC + c
    const int n    = row >> 9;
    const float r = ratios[n];
    const int vw  = min(WDIM, (int)floorf((float)WDIM * r + 0.5f));

    const float* p = g_logits + (size_t)row * TT;
    float v[32];
    float mx = -INFINITY;
    #pragma unroll
    for (int i = 0; i < 32; i++) {
        const int t = lane + i * 32;
        float x = p[t] * SCALE_F;
        if ((t & (WDIM - 1)) >= vw) x = -INFINITY;
        v[i] = x; mx = fmaxf(mx, x);
    }
    #pragma unroll
    for (int off = 16; off > 0; off >>= 1)
        mx = fmaxf(mx, __shfl_xor_sync(0xffffffffu, mx, off));
    float s = 0.0f;
    #pragma unroll
    for (int i = 0; i < 32; i++) { const float e = expf(v[i] - mx); v[i] = e; s += e; }
    #pragma unroll
    for (int off = 16; off > 0; off >>= 1)
        s += __shfl_xor_sync(0xffffffffu, s, off);
    const float inv = 1.0f / s;
    __nv_bfloat16* wh = g_Wh + (size_t)row * TT;
    __nv_bfloat16* wl = g_Wl + (size_t)row * TT;
    #pragma unroll
    for (int i = 0; i < 32; i++) {
        __nv_bfloat16 h, l; split2(v[i] * inv, h, l);
        wh[lane + i * 32] = h; wl[lane + i * 32] = l;
    }
}

// ---------------- GEMM: D[m][nn] = sum_k A[m][k]*B[nn][k] ----------------
// Warp-specialized tcgen05: warps 4-7 fill BK=64 chunks via cp.async into a
// 3-stage ring; warp 0 issues 12 MMAs/chunk (ah*bh + ah*bl + al*bh) paced only
// by the tensor queue. full[s]: cp.async-completion arrivals (count 128);
// empty[s]: per-chunk tcgen05.commit; done: dedicated single-use barrier for
// the final all-MMAs-complete wait (avoids parity aliasing on reused barriers).
// Fallback: fp32 SIMT 8x8 tiles.
#define SM_TMEM  0
#define SM_FULL  8     // 3 x 8B
#define SM_EMPTY 32    // 3 x 8B
#define SM_DONE  56    // 8B, single-use
#define SM_DATA  1024
#define TILE_B   16384
#define STAGES   3
#define GEMM_SMEM (1024 + STAGES * 4 * TILE_B)   // 197632 B

__global__ __launch_bounds__(256, 1)
void gemm_split_kernel(const __nv_bfloat16* __restrict__ Ah, const __nv_bfloat16* __restrict__ Al,
                       const __nv_bfloat16* __restrict__ Bh, const __nv_bfloat16* __restrict__ Bl,
                       float* __restrict__ C, int Kdim, int ldc,
                       size_t sA, size_t sB, size_t sC) {
    extern __shared__ char smem[];
    const int tid = threadIdx.x, wid = tid >> 5, lane = tid & 31;
    const int nz = blockIdx.z, m0 = blockIdx.y * 128, n0 = blockIdx.x * 128;

#if USE_TCGEN05
    const uint32_t sb = smem_to_u32(smem);
    const __nv_bfloat16* src[4];
    src[0] = Ah + nz * sA + (size_t)m0 * Kdim;
    src[1] = Al + nz * sA + (size_t)m0 * Kdim;
    src[2] = Bh + nz * sB + (size_t)n0 * Kdim;
    src[3] = Bl + nz * sB + (size_t)n0 * Kdim;

    if (wid == 0) { TCGEN05_ALLOC(sb + SM_TMEM, 128); TCGEN05_RELINQUISH(); }
    if (tid == 0) {
        #pragma unroll
        for (int s = 0; s < STAGES; s++) {
            MBARRIER_INIT(sb + SM_FULL  + 8 * s, 128);  // filler threads
            MBARRIER_INIT(sb + SM_EMPTY + 8 * s, 1);    // tcgen05 commit
        }
        MBARRIER_INIT(sb + SM_DONE, 1);                 // final completion
    }
    __syncthreads();
    uint32_t tmem;
    asm volatile("ld.shared.b32 %0, [%1];" : "=r"(tmem) : "r"(sb + SM_TMEM));

    const int nch = Kdim >> 6;

    if (wid >= 4) {
        // ---- producer: 128 threads fill 64KB/chunk (32 cp.async each) ----
        const int f  = tid - 128;             // 0..127
        const int r0 = f >> 3, c_ = f & 7;    // per-tile: rows r0, r0+16, ... (8 iters)
        for (int ch = 0; ch < nch; ch++) {
            const int s = ch % STAGES;
            if (ch >= STAGES)
                MBARRIER_WAIT_PARITY(sb + SM_EMPTY + 8 * s, ((ch - STAGES) / STAGES) & 1);
            const int k0 = ch << 6;
            #pragma unroll
            for (int tg = 0; tg < 4; tg++) {
                const uint32_t tb = sb + SM_DATA + (uint32_t)(s * 4 + tg) * TILE_B;
                const __nv_bfloat16* gs = src[tg] + k0;
                #pragma unroll
                for (int i = 0; i < 8; i++) {
                    const int r = r0 + i * 16;
                    const uint32_t dst = tb + SMEM_SWIZZLE_128B((uint32_t)(r * 128 + c_ * 16));
                    CP_ASYNC_16(dst, (const void*)(gs + (size_t)r * Kdim + c_ * 8));
                }
            }
            CP_ASYNC_MBAR_ARRIVE(sb + SM_FULL + 8 * s);
        }
    } else if (wid == 0) {
        // ---- consumer: MMA issue, paced by tensor queue ----
        for (int ch = 0; ch < nch; ch++) {
            const int s = ch % STAGES;
            MBARRIER_WAIT_PARITY(sb + SM_FULL + 8 * s, (ch / STAGES) & 1);
            FENCE_PROXY_ASYNC();
            if (elect_one_pred()) {
                const uint64_t dAh = MAKE_DESC(sb + SM_DATA + (s * 4 + 0) * TILE_B);
                const uint64_t dAl = MAKE_DESC(sb + SM_DATA + (s * 4 + 1) * TILE_B);
                const uint64_t dBh = MAKE_DESC(sb + SM_DATA + (s * 4 + 2) * TILE_B);
                const uint64_t dBl = MAKE_DESC(sb + SM_DATA + (s * 4 + 3) * TILE_B);
                #pragma unroll
                for (int p = 0; p < 3; p++) {
                    const uint64_t da = (p == 2) ? dAl : dAh;
                    const uint64_t db = (p == 1) ? dBl : dBh;
                    #pragma unroll
                    for (int ks = 0; ks < 4; ks++) {
                        const uint32_t en = !(ch == 0 && p == 0 && ks == 0);
                        mma_f16_ss(tmem, da + ks * 2, db + ks * 2, GEMM_IDESC, en);
                    }
                }
                TCGEN05_COMMIT(sb + SM_EMPTY + 8 * s);
            }
        }
        // single-use completion signal: fires when ALL prior MMAs complete
        if (elect_one_pred()) TCGEN05_COMMIT(sb + SM_DONE);
    }
    // ---- all warps: unambiguous final wait (done used exactly once) ----
    MBARRIER_WAIT_PARITY(sb + SM_DONE, 0);
    TCGEN05_FENCE_AFTER();

    if (wid < 4) {
        float* Crow = C + nz * sC + (size_t)(m0 + wid * 32 + lane) * ldc + n0;
        #pragma unroll
        for (int nb = 0; nb < 4; nb++) {
            uint32_t r[32];
            TCGEN05_LD_32X32B_X32(r, tmem + nb * 32);
            TCGEN05_WAIT_LD();
            #pragma unroll
            for (int j = 0; j < 8; j++) {
                float4 v;
                v.x = __uint_as_float(r[j * 4 + 0]);
                v.y = __uint_as_float(r[j * 4 + 1]);
                v.z = __uint_as_float(r[j * 4 + 2]);
                v.w = __uint_as_float(r[j * 4 + 3]);
                *(float4*)(Crow + nb * 32 + j * 4) = v;
            }
        }
        TCGEN05_FENCE_BEFORE();
    }
    __syncthreads();
    if (tid == 0) {
        #pragma unroll
        for (int s = 0; s < STAGES; s++) {
            MBARRIER_INVAL(sb + SM_FULL + 8 * s);
            MBARRIER_INVAL(sb + SM_EMPTY + 8 * s);
        }
        MBARRIER_INVAL(sb + SM_DONE);
    }
    __syncthreads();
    if (wid == 0) TCGEN05_DEALLOC(tmem, 128);

#else
    // ---- SIMT fallback: fp32 (hi+lo) 128x128 tile, 8x8/thread, f32x2 FMA ----
    float* As = (float*)smem;                       // [16][136]
    float* Bs = (float*)(smem + 16 * 136 * 4);      // [16][136]
    const __nv_bfloat16* pAh = Ah + nz * sA + (size_t)m0 * Kdim;
    const __nv_bfloat16* pAl = Al + nz * sA + (size_t)m0 * Kdim;
    const __nv_bfloat16* pBh = Bh + nz * sB + (size_t)n0 * Kdim;
    const __nv_bfloat16* pBl = Bl + nz * sB + (size_t)n0 * Kdim;

    const int tx = tid & 15;
    const int ty = tid >> 4;
    const int lr = tid >> 1;
    const int lk = (tid & 1) * 8;

    unsigned long long acc[8][4];
    #pragma unroll
    for (int i = 0; i < 8; i++)
        #pragma unroll
        for (int j = 0; j < 4; j++) acc[i][j] = 0ull;

    for (int k0 = 0; k0 < Kdim; k0 += 16) {
        {
            uint4 uh = *(const uint4*)(pAh + (size_t)lr * Kdim + k0 + lk);
            uint4 ul = *(const uint4*)(pAl + (size_t)lr * Kdim + k0 + lk);
            const uint32_t hh[4] = {uh.x, uh.y, uh.z, uh.w};
            const uint32_t ll[4] = {ul.x, ul.y, ul.z, ul.w};
            #pragma unroll
            for (int j = 0; j < 4; j++) {
                float2 h = bf2_to_f2(hh[j]), l = bf2_to_f2(ll[j]);
                As[(lk + j * 2 + 0) * 136 + lr] = h.x + l.x;
                As[(lk + j * 2 + 1) * 136 + lr] = h.y + l.y;
            }
        }
        {
            uint4 uh = *(const uint4*)(pBh + (size_t)lr * Kdim + k0 + lk);
            uint4 ul = *(const uint4*)(pBl + (size_t)lr * Kdim + k0 + lk);
            const uint32_t hh[4] = {uh.x, uh.y, uh.z, uh.w};
            const uint32_t ll[4] = {ul.x, ul.y, ul.z, ul.w};
            #pragma unroll
            for (int j = 0; j < 4; j++) {
                float2 h = bf2_to_f2(hh[j]), l = bf2_to_f2(ll[j]);
                Bs[(lk + j * 2 + 0) * 136 + lr] = h.x + l.x;
                Bs[(lk + j * 2 + 1) * 136 + lr] = h.y + l.y;
            }
        }
        __syncthreads();

        #pragma unroll
        for (int kk = 0; kk < 16; kk++) {
            float4 a0 = *(const float4*)&As[kk * 136 + ty * 8 + 0];
            float4 a1 = *(const float4*)&As[kk * 136 + ty * 8 + 4];
            unsigned long long b0 = *(const unsigned long long*)&Bs[kk * 136 + tx * 8 + 0];
            unsigned long long b1 = *(const unsigned long long*)&Bs[kk * 136 + tx * 8 + 2];
            unsigned long long b2 = *(const unsigned long long*)&Bs[kk * 136 + tx * 8 + 4];
            unsigned long long b3 = *(const unsigned long long*)&Bs[kk * 136 + tx * 8 + 6];
            float am[8] = {a0.x, a0.y, a0.z, a0.w, a1.x, a1.y, a1.z, a1.w};
            #pragma unroll
            for (int m = 0; m < 8; m++) {
                unsigned long long A2 = pack_dup(am[m]);
                FMA2(acc[m][0], A2, b0);
                FMA2(acc[m][1], A2, b1);
                FMA2(acc[m][2], A2, b2);
                FMA2(acc[m][3], A2, b3);
            }
        }
        __syncthreads();
    }

    #pragma unroll
    for (int m = 0; m < 8; m++) {
        float* Crow = C + nz * sC + (size_t)(m0 + ty * 8 + m) * ldc + n0 + tx * 8;
        #pragma unroll
        for (int p = 0; p < 4; p++)
            *(unsigned long long*)(Crow + p * 2) = acc[m][p];
    }
#endif
}

// ---------------- launch ----------------
extern "C" void kernel_launch(void* const* d_in, const int* in_sizes, int n_in,
                              void* d_out, int out_size) {
    const float* q      = (const float*)d_in[0];
    const float* k      = (const float*)d_in[1];
    const float* v      = (const float*)d_in[2];
    const float* ratios = (const float*)d_in[3];
    float* out = (float*)d_out;
    (void)in_sizes; (void)n_in; (void)out_size;

    float* lg; __nv_bfloat16 *qh, *ql, *kh, *kl, *vh, *vl, *wh, *wl;
    cudaGetSymbolAddress((void**)&lg, g_logits);
    cudaGetSymbolAddress((void**)&qh, g_Qth); cudaGetSymbolAddress((void**)&ql, g_Qtl);
    cudaGetSymbolAddress((void**)&kh, g_Kth); cudaGetSymbolAddress((void**)&kl, g_Ktl);
    cudaGetSymbolAddress((void**)&vh, g_Vh);  cudaGetSymbolAddress((void**)&vl, g_Vl);
    cudaGetSymbolAddress((void**)&wh, g_Wh);  cudaGetSymbolAddress((void**)&wl, g_Wl);

    cudaFuncSetAttribute(gemm_split_kernel,
                         cudaFuncAttributeMaxDynamicSharedMemorySize, GEMM_SMEM);

    // pre-pass: Qt[c][d], Kt[t][d], V split
    transpose_split_kernel<<<dim3(CC / 32, DD / 32, NB), dim3(32, 8)>>>(q, qh, ql, DD, CC);
    transpose_split_kernel<<<dim3(TT / 32, DD / 32, NB), dim3(32, 8)>>>(k, kh, kl, DD, TT);
    split_kernel<<<(NB * DD * TT / 4) / 256, 256>>>(v, vh, vl);

    // GEMM1: logits[c][t] = Qt[c][:] . Kt[t][:]   (K=512)
    gemm_split_kernel<<<dim3(TT / 128, CC / 128, NB), 256, GEMM_SMEM>>>(
        qh, ql, kh, kl, lg, DD, TT,
        (size_t)CC * DD, (size_t)TT * DD, (size_t)CC * TT);

    softmax_kernel<<<(NB * CC) / 8, 256>>>(ratios);

    // GEMM2: out[dd][c] = V[dd][:] . W[c][:]      (K=1024)
    gemm_split_kernel<<<dim3(CC / 128, DD / 128, NB), 256, GEMM_SMEM>>>(
        vh, vl, wh, wl, out, TT, CC,
        (size_t)DD * TT, (size_t)CC * TT, (size_t)DD * CC);
}